// round 16
// baseline (speedup 1.0000x reference)
#include <cuda_runtime.h>
#include <cuda_fp16.h>
#include <cstdint>
#include <cstddef>

// Problem constants (fixed shapes for this problem)
#define S_MAX   4096
#define D_DIM   256
#define NH      8
#define HD      32
#define H_DIM   256

// ---------------- device scratch (no cudaMalloc allowed) ----------------
__device__ float  g_q[S_MAX * H_DIM];             // q = queries@Wq + bq
__device__ float  g_qk[S_MAX * NH * D_DIM];       // qk[s][h][j]
__device__ float  g_qb[S_MAX * NH];               // qb[s][h]
__device__ __half g_Ahat[S_MAX * NH * D_DIM];     // A/denom (fp16)
__device__ float  g_pooled[S_MAX * H_DIM];
__device__ int    g_off[S_MAX + 1];

// ---------------- cp.async helpers ----------------
__device__ __forceinline__ void cpa16(float* dst, const float* src) {
    uint32_t d = (uint32_t)__cvta_generic_to_shared(dst);
    asm volatile("cp.async.cg.shared.global [%0], [%1], 16;" :: "r"(d), "l"(src));
}
#define CPA_COMMIT() asm volatile("cp.async.commit_group;")
#define CPA_WAIT0()  asm volatile("cp.async.wait_group 0;")

// ---------------- tf32 3x-split helpers (mask-split: 2 ops) -------------
__device__ __forceinline__ void tf32_split(float x, uint32_t& hi, uint32_t& lo) {
    hi = __float_as_uint(x) & 0xFFFFE000u;
    lo = __float_as_uint(x - __uint_as_float(hi));
}
__device__ __forceinline__ void split4(float4 v, uint4& h, uint4& l) {
    tf32_split(v.x, h.x, l.x); tf32_split(v.y, h.y, l.y);
    tf32_split(v.z, h.z, l.z); tf32_split(v.w, h.w, l.w);
}
__device__ __forceinline__ void mma_tf32(float* c, const uint32_t* a, const uint32_t* b) {
    asm("mma.sync.aligned.m16n8k8.row.col.f32.tf32.tf32.f32 "
        "{%0,%1,%2,%3}, {%4,%5,%6,%7}, {%8,%9}, {%0,%1,%2,%3};"
        : "+f"(c[0]), "+f"(c[1]), "+f"(c[2]), "+f"(c[3])
        : "r"(a[0]), "r"(a[1]), "r"(a[2]), "r"(a[3]),
          "r"(b[0]), "r"(b[1]));
}
__device__ __forceinline__ void mma3(float* c, const uint32_t* ah, const uint32_t* al,
                                     const uint32_t* bh, const uint32_t* bl) {
    mma_tf32(c, ah, bh);
    mma_tf32(c, ah, bl);
    mma_tf32(c, al, bh);
}
// unpack 8 halves (one uint4) into two float4s
__device__ __forceinline__ void half8_to_f4(uint4 rv, float4& a, float4& b) {
    const __half2* hp = reinterpret_cast<const __half2*>(&rv);
    float2 f0 = __half22float2(hp[0]);
    float2 f1 = __half22float2(hp[1]);
    float2 f2 = __half22float2(hp[2]);
    float2 f3 = __half22float2(hp[3]);
    a = make_float4(f0.x, f0.y, f1.x, f1.y);
    b = make_float4(f2.x, f2.y, f3.x, f3.y);
}

// ---------------- K0: segment offsets via binary search (idx sorted) ----
__global__ void k_offsets(const int* __restrict__ map, int N, int S) {
    int s = blockIdx.x * blockDim.x + threadIdx.x;
    if (s > S) return;
    int lo = 0, hi = N;
    while (lo < hi) {
        int mid = (lo + hi) >> 1;
        if (map[mid] < s) lo = mid + 1; else hi = mid;
    }
    g_off[s] = lo;
}

// ---------- tensor GEMM (3xTF32, pre-split smem): C = A@B + bias --------
__global__ void __launch_bounds__(256)
k_gemm_tf32(const float* __restrict__ A, const float* __restrict__ B,
            const float* __restrict__ bias, float* __restrict__ C,
            int M, int K, int N) {
    __shared__ uint32_t Ah[64][36], Al[64][36];   // m-major: bank 4*gid+tig
    __shared__ uint32_t Bh[32][72], Bl[32][72];   // k-major: bank 8*tig+gid
    int t = threadIdx.x;
    int lane = t & 31, w = t >> 5;
    int gid = lane >> 2, tig = lane & 3;
    int wm = w & 1, wn = w >> 1;
    int bm = blockIdx.x * 64, bn = blockIdx.y * 64;
    int ar = t >> 2, ac = (t & 3) * 8;
    int br = t >> 3, bc = (t & 7) * 8;

    float c[2][2][4] = {};
    float4 ra0, ra1, rb0, rb1;

    ra0 = *(const float4*)&A[(size_t)(bm + ar) * K + ac];
    ra1 = *(const float4*)&A[(size_t)(bm + ar) * K + ac + 4];
    rb0 = *(const float4*)&B[(size_t)br * N + bn + bc];
    rb1 = *(const float4*)&B[(size_t)br * N + bn + bc + 4];

    int nc = K / 32;
    for (int ch = 0; ch < nc; ch++) {
        if (ch > 0) __syncthreads();
        {
            uint4 h, l;
            split4(ra0, h, l);
            *(uint4*)&Ah[ar][ac] = h;     *(uint4*)&Al[ar][ac] = l;
            split4(ra1, h, l);
            *(uint4*)&Ah[ar][ac + 4] = h; *(uint4*)&Al[ar][ac + 4] = l;
            split4(rb0, h, l);
            *(uint4*)&Bh[br][bc] = h;     *(uint4*)&Bl[br][bc] = l;
            split4(rb1, h, l);
            *(uint4*)&Bh[br][bc + 4] = h; *(uint4*)&Bl[br][bc + 4] = l;
        }
        __syncthreads();
        if (ch + 1 < nc) {
            int k0 = (ch + 1) * 32;
            ra0 = *(const float4*)&A[(size_t)(bm + ar) * K + k0 + ac];
            ra1 = *(const float4*)&A[(size_t)(bm + ar) * K + k0 + ac + 4];
            rb0 = *(const float4*)&B[(size_t)(k0 + br) * N + bn + bc];
            rb1 = *(const float4*)&B[(size_t)(k0 + br) * N + bn + bc + 4];
        }
#pragma unroll
        for (int ks = 0; ks < 4; ks++) {
            int k8 = ks * 8;
            uint32_t ah[2][4], al[2][4], bh[2][2], bl[2][2];
#pragma unroll
            for (int ma = 0; ma < 2; ma++) {
                int m0 = wm * 32 + ma * 16 + gid;
                ah[ma][0] = Ah[m0][k8 + tig];     al[ma][0] = Al[m0][k8 + tig];
                ah[ma][1] = Ah[m0 + 8][k8 + tig]; al[ma][1] = Al[m0 + 8][k8 + tig];
                ah[ma][2] = Ah[m0][k8 + tig + 4]; al[ma][2] = Al[m0][k8 + tig + 4];
                ah[ma][3] = Ah[m0 + 8][k8 + tig + 4]; al[ma][3] = Al[m0 + 8][k8 + tig + 4];
            }
#pragma unroll
            for (int na = 0; na < 2; na++) {
                int n0 = wn * 16 + na * 8 + gid;
                bh[na][0] = Bh[k8 + tig][n0];     bl[na][0] = Bl[k8 + tig][n0];
                bh[na][1] = Bh[k8 + tig + 4][n0]; bl[na][1] = Bl[k8 + tig + 4][n0];
            }
#pragma unroll
            for (int ma = 0; ma < 2; ma++)
#pragma unroll
                for (int na = 0; na < 2; na++)
                    mma3(c[ma][na], ah[ma], al[ma], bh[na], bl[na]);
        }
    }

#pragma unroll
    for (int ma = 0; ma < 2; ma++)
#pragma unroll
        for (int na = 0; na < 2; na++) {
            int row = bm + wm * 32 + ma * 16 + gid;
            int col = bn + wn * 16 + na * 8 + 2 * tig;
            float2 bv = *(const float2*)&bias[col];
            float2 o0; o0.x = c[ma][na][0] + bv.x; o0.y = c[ma][na][1] + bv.y;
            float2 o1; o1.x = c[ma][na][2] + bv.x; o1.y = c[ma][na][3] + bv.y;
            *(float2*)&C[(size_t)row * N + col]       = o0;
            *(float2*)&C[(size_t)(row + 8) * N + col] = o1;
        }
}

// ---------- K2 tensor: qk[s][h][j] = Q_h[s,:] . Wk_h[j,:]  (K=32) -------
__global__ void __launch_bounds__(256)
k_qk_tf32(const float* __restrict__ Wkv, const float* __restrict__ bkv) {
    __shared__ uint32_t Ah[64][36], Al[64][36];   // q slice  [s][d]
    __shared__ uint32_t Nh[64][36], Nl[64][36];   // Wk slice [j][d]
    int t = threadIdx.x;
    int lane = t & 31, w = t >> 5;
    int gid = lane >> 2, tig = lane & 3;
    int wm = w & 1, wn = w >> 1;
    int bm = blockIdx.x * 64, bnj = blockIdx.y * 64, h = blockIdx.z;
    int r = t >> 2, cq = (t & 3) * 8;

    {
        float4 v0 = *(const float4*)&g_q[(size_t)(bm + r) * H_DIM + h * HD + cq];
        float4 v1 = *(const float4*)&g_q[(size_t)(bm + r) * H_DIM + h * HD + cq + 4];
        uint4 hh, ll;
        split4(v0, hh, ll); *(uint4*)&Ah[r][cq] = hh;     *(uint4*)&Al[r][cq] = ll;
        split4(v1, hh, ll); *(uint4*)&Ah[r][cq + 4] = hh; *(uint4*)&Al[r][cq + 4] = ll;
        float4 w0 = *(const float4*)&Wkv[(size_t)(bnj + r) * 512 + h * HD + cq];
        float4 w1 = *(const float4*)&Wkv[(size_t)(bnj + r) * 512 + h * HD + cq + 4];
        split4(w0, hh, ll); *(uint4*)&Nh[r][cq] = hh;     *(uint4*)&Nl[r][cq] = ll;
        split4(w1, hh, ll); *(uint4*)&Nh[r][cq + 4] = hh; *(uint4*)&Nl[r][cq + 4] = ll;
    }
    __syncthreads();

    float c[2][2][4] = {};
#pragma unroll
    for (int ks = 0; ks < 4; ks++) {
        int k8 = ks * 8;
        uint32_t ah[2][4], al[2][4], bh[2][2], bl[2][2];
#pragma unroll
        for (int ma = 0; ma < 2; ma++) {
            int m0 = wm * 32 + ma * 16 + gid;
            ah[ma][0] = Ah[m0][k8 + tig];         al[ma][0] = Al[m0][k8 + tig];
            ah[ma][1] = Ah[m0 + 8][k8 + tig];     al[ma][1] = Al[m0 + 8][k8 + tig];
            ah[ma][2] = Ah[m0][k8 + tig + 4];     al[ma][2] = Al[m0][k8 + tig + 4];
            ah[ma][3] = Ah[m0 + 8][k8 + tig + 4]; al[ma][3] = Al[m0 + 8][k8 + tig + 4];
        }
#pragma unroll
        for (int na = 0; na < 2; na++) {
            int n0 = wn * 16 + na * 8 + gid;
            bh[na][0] = Nh[n0][k8 + tig];     bl[na][0] = Nl[n0][k8 + tig];
            bh[na][1] = Nh[n0][k8 + tig + 4]; bl[na][1] = Nl[n0][k8 + tig + 4];
        }
#pragma unroll
        for (int ma = 0; ma < 2; ma++)
#pragma unroll
            for (int na = 0; na < 2; na++)
                mma3(c[ma][na], ah[ma], al[ma], bh[na], bl[na]);
    }

#pragma unroll
    for (int ma = 0; ma < 2; ma++)
#pragma unroll
        for (int na = 0; na < 2; na++) {
            int srow = bm + wm * 32 + ma * 16 + gid;
            int col  = bnj + wn * 16 + na * 8 + 2 * tig;
            float2 o0; o0.x = c[ma][na][0]; o0.y = c[ma][na][1];
            float2 o1; o1.x = c[ma][na][2]; o1.y = c[ma][na][3];
            *(float2*)&g_qk[(size_t)srow * (NH * D_DIM) + h * D_DIM + col]       = o0;
            *(float2*)&g_qk[(size_t)(srow + 8) * (NH * D_DIM) + h * D_DIM + col] = o1;
        }

    if (blockIdx.y == 0 && t < 64) {
        int s = bm + t;
        float acc = 0.f;
#pragma unroll
        for (int d = 0; d < HD; d++)
            acc += g_q[(size_t)s * H_DIM + h * HD + d] * bkv[h * HD + d];
        g_qb[s * NH + h] = acc;
    }
}

// ---------- K4 tensor: pooled_h = Ahat_h[64x256] @ Wv_h[256x32] ---------
__global__ void __launch_bounds__(256)
k_pool_tf32(const float* __restrict__ Wkv, const float* __restrict__ bkv) {
    __shared__ uint32_t Ah[64][36], Al[64][36];
    __shared__ uint32_t Bh[32][40], Bl[32][40];
    int t = threadIdx.x;
    int lane = t & 31, w = t >> 5;
    int gid = lane >> 2, tig = lane & 3;
    int wm = w & 3, wn = w >> 2;
    int bm = blockIdx.x * 64, h = blockIdx.y;
    int arr = t >> 2, acq = (t & 3) * 8;
    int bkk = t >> 3, bn4 = (t & 7) * 4;

    const __half* Abase = g_Ahat + (size_t)bm * (NH * D_DIM) + h * D_DIM;
    float c[2][4] = {};
    uint4 rha;
    float4 rb;

    rha = *(const uint4*)&Abase[(size_t)arr * (NH * D_DIM) + acq];
    rb  = *(const float4*)&Wkv[(size_t)bkk * 512 + 256 + h * HD + bn4];

    for (int ch = 0; ch < 8; ch++) {
        if (ch > 0) __syncthreads();
        {
            float4 ra0, ra1;
            half8_to_f4(rha, ra0, ra1);
            uint4 hh, ll;
            split4(ra0, hh, ll);
            *(uint4*)&Ah[arr][acq] = hh;     *(uint4*)&Al[arr][acq] = ll;
            split4(ra1, hh, ll);
            *(uint4*)&Ah[arr][acq + 4] = hh; *(uint4*)&Al[arr][acq + 4] = ll;
            split4(rb, hh, ll);
            *(uint4*)&Bh[bkk][bn4] = hh;     *(uint4*)&Bl[bkk][bn4] = ll;
        }
        __syncthreads();
        if (ch + 1 < 8) {
            int k0 = (ch + 1) * 32;
            rha = *(const uint4*)&Abase[(size_t)arr * (NH * D_DIM) + k0 + acq];
            rb  = *(const float4*)&Wkv[(size_t)(k0 + bkk) * 512 + 256 + h * HD + bn4];
        }
#pragma unroll
        for (int ks = 0; ks < 4; ks++) {
            int k8 = ks * 8;
            uint32_t ah[4], al[4], bh[2][2], bl[2][2];
            int m0 = wm * 16 + gid;
            ah[0] = Ah[m0][k8 + tig];         al[0] = Al[m0][k8 + tig];
            ah[1] = Ah[m0 + 8][k8 + tig];     al[1] = Al[m0 + 8][k8 + tig];
            ah[2] = Ah[m0][k8 + tig + 4];     al[2] = Al[m0][k8 + tig + 4];
            ah[3] = Ah[m0 + 8][k8 + tig + 4]; al[3] = Al[m0 + 8][k8 + tig + 4];
#pragma unroll
            for (int na = 0; na < 2; na++) {
                int n0 = wn * 16 + na * 8 + gid;
                bh[na][0] = Bh[k8 + tig][n0];     bl[na][0] = Bl[k8 + tig][n0];
                bh[na][1] = Bh[k8 + tig + 4][n0]; bl[na][1] = Bl[k8 + tig + 4][n0];
            }
#pragma unroll
            for (int na = 0; na < 2; na++)
                mma3(c[na], ah, al, bh[na], bl[na]);
        }
    }

#pragma unroll
    for (int na = 0; na < 2; na++) {
        int row = bm + wm * 16 + gid;
        int col = wn * 16 + na * 8 + 2 * tig;
        float2 bv = *(const float2*)&bkv[256 + h * HD + col];
        bool ne0 = g_off[row + 1] > g_off[row];
        bool ne1 = g_off[row + 9] > g_off[row + 8];
        float2 o0, o1;
        o0.x = c[na][0] + (ne0 ? bv.x : 0.f); o0.y = c[na][1] + (ne0 ? bv.y : 0.f);
        o1.x = c[na][2] + (ne1 ? bv.x : 0.f); o1.y = c[na][3] + (ne1 ? bv.y : 0.f);
        *(float2*)&g_pooled[(size_t)row * H_DIM + h * HD + col]       = o0;
        *(float2*)&g_pooled[(size_t)(row + 8) * H_DIM + h * HD + col] = o1;
    }
}

// ---------------- K3: PERSISTENT streaming softmax-pool -----------------
// grid = 4*148 = 592 persistent blocks; each grid-strides over samples.
// Cross-sample prefetch: after a sample's last A-update barrier (sQK and
// sE are dead), cp.async the NEXT sample's qk + qb + first E tile so they
// land during the epilogue — removes the exposed per-sample prologue and
// all wave transitions. d-sum is lane-local in the loop, warp-reduced once
// per sample in the epilogue (was 5 shuffles per tile). Ahat out in fp16.
// Empty samples still pass through the sample-start WAIT0 before sQK is
// re-targeted (no overlapping async writes to the same smem).
#define ATTN_SMEM_FLOATS (12896)
#define SE_STRIDE 260
#define ATTN_GRID 592

__global__ void __launch_bounds__(256, 4)
k_attn(const float* __restrict__ emb, float scale, int S) {
    extern __shared__ float dyn[];
    float* sQK   = dyn;
    float* sE    = dyn + 2080;
    float* sPart = dyn + 10400;
    float* sP    = dyn + 12496;
    float* sD    = dyn + 12880;
    float* sQBs  = dyn + 12888;

    int t = threadIdx.x;
    int lane = t & 31, w = t >> 5;
    int gid = lane >> 2, tig = lane & 3;
    int j0 = w * 32;

    // prefetch first sample handled by this block
    int s0 = blockIdx.x;
    if (s0 < S) {
        int start = g_off[s0], end = g_off[s0 + 1];
        for (int i = t; i < 512; i += 256) {
            int h = i >> 6, j = (i & 63) * 4;
            cpa16(&sQK[h * SE_STRIDE + j], g_qk + (size_t)s0 * 2048 + (size_t)i * 4);
        }
        if (t < 2) cpa16(&sQBs[t * 4], g_qb + s0 * NH + t * 4);
        if (start < end) {
            int T = min(32, end - start);
            for (int i = t; i < T * 64; i += 256) {
                int e = i >> 6, j4 = (i & 63) * 4;
                cpa16(&sE[e * SE_STRIDE + j4], emb + (size_t)(start + e) * D_DIM + j4);
            }
        }
    }
    CPA_COMMIT();

    for (int s = s0; s < S; s += gridDim.x) {
        int start = g_off[s], end = g_off[s + 1];
        int snext = s + gridDim.x;

        float c[2][4] = {};
        float d_lane = 0.f;

        CPA_WAIT0();
        __syncthreads();     // this sample's qk/qb/E0 resident

        for (int t0 = start; t0 < end; t0 += 32) {
            int T = min(32, end - t0);
            if (t0 > start) {
                CPA_WAIT0();
                __syncthreads();   // next tile resident; prior reads done
            }

            if (T < 32) {    // zero tail rows so 0*garbage can't make NaN
                for (int i = t; i < (32 - T) * 64; i += 256) {
                    int e = T + (i >> 6), j4 = (i & 63) * 4;
                    *(float4*)&sE[e * SE_STRIDE + j4] = make_float4(0.f, 0.f, 0.f, 0.f);
                }
                __syncthreads();
            }

            // ---- score partials via tensor cores
            {
                float cs[2][4] = {};
#pragma unroll
                for (int ks = 0; ks < 4; ks++) {
                    int jk = j0 + ks * 8;
                    uint32_t bh[2], bl[2];
                    tf32_split(sQK[gid * SE_STRIDE + jk + tig],     bh[0], bl[0]);
                    tf32_split(sQK[gid * SE_STRIDE + jk + tig + 4], bh[1], bl[1]);
#pragma unroll
                    for (int ma = 0; ma < 2; ma++) {
                        int e0 = ma * 16 + gid;
                        uint32_t ah[4], al[4];
                        tf32_split(sE[e0 * SE_STRIDE + jk + tig],           ah[0], al[0]);
                        tf32_split(sE[(e0 + 8) * SE_STRIDE + jk + tig],     ah[1], al[1]);
                        tf32_split(sE[e0 * SE_STRIDE + jk + tig + 4],       ah[2], al[2]);
                        tf32_split(sE[(e0 + 8) * SE_STRIDE + jk + tig + 4], ah[3], al[3]);
                        mma3(cs[ma], ah, al, bh, bl);
                    }
                }
#pragma unroll
                for (int ma = 0; ma < 2; ma++) {
                    int e0 = ma * 16 + gid;
                    sPart[e0 * 65 + (2 * tig) * 8 + w]           = cs[ma][0];
                    sPart[e0 * 65 + (2 * tig + 1) * 8 + w]       = cs[ma][1];
                    sPart[(e0 + 8) * 65 + (2 * tig) * 8 + w]     = cs[ma][2];
                    sPart[(e0 + 8) * 65 + (2 * tig + 1) * 8 + w] = cs[ma][3];
                }
            }
            __syncthreads();

            // ---- reduce partials + exp; lane-local d accumulation
            float p = 0.f;
            if (lane < T) {
                float sum = 0.f;
#pragma unroll
                for (int i = 0; i < 8; i++) sum += sPart[lane * 65 + w * 8 + i];
                p = __expf(scale * (sum + sQBs[w]));
            }
            sP[lane * 12 + w] = p;
            d_lane += p;
            __syncthreads();

            // ---- A update via tensor cores
#pragma unroll
            for (int ks = 0; ks < 4; ks++) {
                int e0 = 8 * ks + tig;
                uint32_t bh[2], bl[2];
                tf32_split(sP[e0 * 12 + gid],       bh[0], bl[0]);
                tf32_split(sP[(e0 + 4) * 12 + gid], bh[1], bl[1]);
#pragma unroll
                for (int ma = 0; ma < 2; ma++) {
                    int jbv = j0 + ma * 16 + gid;
                    uint32_t ah[4], al[4];
                    tf32_split(sE[e0 * SE_STRIDE + jbv],           ah[0], al[0]);
                    tf32_split(sE[e0 * SE_STRIDE + jbv + 8],       ah[1], al[1]);
                    tf32_split(sE[(e0 + 4) * SE_STRIDE + jbv],     ah[2], al[2]);
                    tf32_split(sE[(e0 + 4) * SE_STRIDE + jbv + 8], ah[3], al[3]);
                    mma3(c[ma], ah, al, bh, bl);
                }
            }
            __syncthreads();   // all sE reads done; safe to refill

            if (t0 + 32 < end) {
                int Tn = min(32, end - (t0 + 32));
                for (int i = t; i < Tn * 64; i += 256) {
                    int e = i >> 6, j4 = (i & 63) * 4;
                    cpa16(&sE[e * SE_STRIDE + j4],
                          emb + (size_t)(t0 + 32 + e) * D_DIM + j4);
                }
            }
            CPA_COMMIT();
        }

        // ---- cross-sample prefetch: sQK/sE dead past the last barrier
        if (snext < S) {
            int nstart = g_off[snext], nend = g_off[snext + 1];
            for (int i = t; i < 512; i += 256) {
                int h = i >> 6, j = (i & 63) * 4;
                cpa16(&sQK[h * SE_STRIDE + j], g_qk + (size_t)snext * 2048 + (size_t)i * 4);
            }
            if (t < 2) cpa16(&sQBs[t * 4], g_qb + snext * NH + t * 4);
            if (nstart < nend) {
                int T = min(32, nend - nstart);
                for (int i = t; i < T * 64; i += 256) {
                    int e = i >> 6, j4 = (i & 63) * 4;
                    cpa16(&sE[e * SE_STRIDE + j4], emb + (size_t)(nstart + e) * D_DIM + j4);
                }
            }
        }
        CPA_COMMIT();

        // ---- epilogue: once-per-sample d reduce + fp16 Ahat write
        {
            float dsum = d_lane;
#pragma unroll
            for (int o = 16; o; o >>= 1) dsum += __shfl_xor_sync(0xffffffffu, dsum, o);
            if (lane == 0) sD[w] = dsum;
        }
        __syncthreads();
        {
            float dh0 = sD[2 * tig],     rdh0 = (dh0 > 0.f) ? (1.0f / dh0) : 0.f;
            float dh1 = sD[2 * tig + 1], rdh1 = (dh1 > 0.f) ? (1.0f / dh1) : 0.f;
            __half* outp = g_Ahat + (size_t)s * (NH * D_DIM);
#pragma unroll
            for (int ma = 0; ma < 2; ma++) {
                int j = j0 + ma * 16 + gid;
                outp[(2 * tig) * D_DIM + j]         = __float2half_rn(c[ma][0] * rdh0);
                outp[(2 * tig + 1) * D_DIM + j]     = __float2half_rn(c[ma][1] * rdh1);
                outp[(2 * tig) * D_DIM + j + 8]     = __float2half_rn(c[ma][2] * rdh0);
                outp[(2 * tig + 1) * D_DIM + j + 8] = __float2half_rn(c[ma][3] * rdh1);
            }
        }
        // next write to sD is after >=1 barrier in the next iteration
    }
}

// ---------------- launch ----------------
extern "C" void kernel_launch(void* const* d_in, const int* in_sizes, int n_in,
                              void* d_out, int out_size) {
    const float* queries = (const float*)d_in[0];
    const float* emb     = (const float*)d_in[1];
    const int*   map     = (const int*)  d_in[2];
    // num_samples may or may not be materialized as a device input
    int base = (n_in >= 10 && in_sizes[3] < 16) ? 4 : 3;
    const float* Wq  = (const float*)d_in[base + 0];
    const float* bq  = (const float*)d_in[base + 1];
    const float* Wkv = (const float*)d_in[base + 2];
    const float* bkv = (const float*)d_in[base + 3];
    const float* Wo  = (const float*)d_in[base + 4];
    const float* bo  = (const float*)d_in[base + 5];
    float* out = (float*)d_out;

    int S = in_sizes[0] / D_DIM;     // 4096
    int N = in_sizes[1] / D_DIM;     // 262144
    float scale = 0.17677669529663687f;   // 1/sqrt(32)

    float* dq      = nullptr; cudaGetSymbolAddress((void**)&dq,      g_q);
    float* dpooled = nullptr; cudaGetSymbolAddress((void**)&dpooled, g_pooled);

    cudaFuncSetAttribute(k_attn, cudaFuncAttributeMaxDynamicSharedMemorySize,
                         ATTN_SMEM_FLOATS * 4);

    // K0: segment offsets
    k_offsets<<<(S + 1 + 255) / 256, 256>>>(map, N, S);
    // K1: q projection (tensor core, 3xTF32)
    {
        dim3 grid(S / 64, H_DIM / 64);
        k_gemm_tf32<<<grid, 256>>>(queries, Wq, bq, dq, S, D_DIM, H_DIM);
    }
    // K2: qk/qb precompute (tensor core)
    {
        dim3 grid(S / 64, D_DIM / 64, NH);
        k_qk_tf32<<<grid, 256>>>(Wkv, bkv);
    }
    // K3: persistent streaming attention with cross-sample prefetch
    k_attn<<<ATTN_GRID, 256, ATTN_SMEM_FLOATS * 4>>>(emb, scale, S);
    // K4: pooled projection through Wv (tensor core, fp16 Ahat read)
    {
        dim3 grid(S / 64, NH);
        k_pool_tf32<<<grid, 256>>>(Wkv, bkv);
    }
    // K5: output projection (tensor core, 3xTF32)
    {
        dim3 grid(S / 64, H_DIM / 64);
        k_gemm_tf32<<<grid, 256>>>(dpooled, Wo, bo, out, S, H_DIM, H_DIM);
    }
}

// round 17
// speedup vs baseline: 1.0574x; 1.0574x over previous
#include <cuda_runtime.h>
#include <cuda_fp16.h>
#include <cstdint>
#include <cstddef>

// Problem constants (fixed shapes for this problem)
#define S_MAX   4096
#define D_DIM   256
#define NH      8
#define HD      32
#define H_DIM   256

// ---------------- device scratch (no cudaMalloc allowed) ----------------
__device__ float  g_q[S_MAX * H_DIM];             // q = queries@Wq + bq
__device__ float  g_qk[S_MAX * NH * D_DIM];       // qk[s][h][j]
__device__ float  g_qb[S_MAX * NH];               // qb[s][h]
__device__ __half g_Ahat[S_MAX * NH * D_DIM];     // A/denom (fp16)
__device__ float  g_pooled[S_MAX * H_DIM];
__device__ int    g_off[S_MAX + 1];

// ---------------- cp.async helpers ----------------
__device__ __forceinline__ void cpa16(float* dst, const float* src) {
    uint32_t d = (uint32_t)__cvta_generic_to_shared(dst);
    asm volatile("cp.async.cg.shared.global [%0], [%1], 16;" :: "r"(d), "l"(src));
}
#define CPA_COMMIT() asm volatile("cp.async.commit_group;")
#define CPA_WAIT0()  asm volatile("cp.async.wait_group 0;")

// ---------------- tf32 3x-split helpers (mask-split: 2 ops) -------------
__device__ __forceinline__ void tf32_split(float x, uint32_t& hi, uint32_t& lo) {
    hi = __float_as_uint(x) & 0xFFFFE000u;
    lo = __float_as_uint(x - __uint_as_float(hi));
}
__device__ __forceinline__ void split4(float4 v, uint4& h, uint4& l) {
    tf32_split(v.x, h.x, l.x); tf32_split(v.y, h.y, l.y);
    tf32_split(v.z, h.z, l.z); tf32_split(v.w, h.w, l.w);
}
__device__ __forceinline__ void mma_tf32(float* c, const uint32_t* a, const uint32_t* b) {
    asm("mma.sync.aligned.m16n8k8.row.col.f32.tf32.tf32.f32 "
        "{%0,%1,%2,%3}, {%4,%5,%6,%7}, {%8,%9}, {%0,%1,%2,%3};"
        : "+f"(c[0]), "+f"(c[1]), "+f"(c[2]), "+f"(c[3])
        : "r"(a[0]), "r"(a[1]), "r"(a[2]), "r"(a[3]),
          "r"(b[0]), "r"(b[1]));
}
__device__ __forceinline__ void mma3(float* c, const uint32_t* ah, const uint32_t* al,
                                     const uint32_t* bh, const uint32_t* bl) {
    mma_tf32(c, ah, bh);
    mma_tf32(c, ah, bl);
    mma_tf32(c, al, bh);
}
// unpack 8 halves (one uint4) into two float4s
__device__ __forceinline__ void half8_to_f4(uint4 rv, float4& a, float4& b) {
    const __half2* hp = reinterpret_cast<const __half2*>(&rv);
    float2 f0 = __half22float2(hp[0]);
    float2 f1 = __half22float2(hp[1]);
    float2 f2 = __half22float2(hp[2]);
    float2 f3 = __half22float2(hp[3]);
    a = make_float4(f0.x, f0.y, f1.x, f1.y);
    b = make_float4(f2.x, f2.y, f3.x, f3.y);
}

// ---------------- K0: segment offsets via binary search (idx sorted) ----
__global__ void k_offsets(const int* __restrict__ map, int N, int S) {
    int s = blockIdx.x * blockDim.x + threadIdx.x;
    if (s > S) return;
    int lo = 0, hi = N;
    while (lo < hi) {
        int mid = (lo + hi) >> 1;
        if (map[mid] < s) lo = mid + 1; else hi = mid;
    }
    g_off[s] = lo;
}

// ---------- tensor GEMM (3xTF32, pre-split smem): C = A@B + bias --------
__global__ void __launch_bounds__(256)
k_gemm_tf32(const float* __restrict__ A, const float* __restrict__ B,
            const float* __restrict__ bias, float* __restrict__ C,
            int M, int K, int N) {
    __shared__ uint32_t Ah[64][36], Al[64][36];   // m-major: bank 4*gid+tig
    __shared__ uint32_t Bh[32][72], Bl[32][72];   // k-major: bank 8*tig+gid
    int t = threadIdx.x;
    int lane = t & 31, w = t >> 5;
    int gid = lane >> 2, tig = lane & 3;
    int wm = w & 1, wn = w >> 1;
    int bm = blockIdx.x * 64, bn = blockIdx.y * 64;
    int ar = t >> 2, ac = (t & 3) * 8;
    int br = t >> 3, bc = (t & 7) * 8;

    float c[2][2][4] = {};
    float4 ra0, ra1, rb0, rb1;

    ra0 = *(const float4*)&A[(size_t)(bm + ar) * K + ac];
    ra1 = *(const float4*)&A[(size_t)(bm + ar) * K + ac + 4];
    rb0 = *(const float4*)&B[(size_t)br * N + bn + bc];
    rb1 = *(const float4*)&B[(size_t)br * N + bn + bc + 4];

    int nc = K / 32;
    for (int ch = 0; ch < nc; ch++) {
        if (ch > 0) __syncthreads();
        {
            uint4 h, l;
            split4(ra0, h, l);
            *(uint4*)&Ah[ar][ac] = h;     *(uint4*)&Al[ar][ac] = l;
            split4(ra1, h, l);
            *(uint4*)&Ah[ar][ac + 4] = h; *(uint4*)&Al[ar][ac + 4] = l;
            split4(rb0, h, l);
            *(uint4*)&Bh[br][bc] = h;     *(uint4*)&Bl[br][bc] = l;
            split4(rb1, h, l);
            *(uint4*)&Bh[br][bc + 4] = h; *(uint4*)&Bl[br][bc + 4] = l;
        }
        __syncthreads();
        if (ch + 1 < nc) {
            int k0 = (ch + 1) * 32;
            ra0 = *(const float4*)&A[(size_t)(bm + ar) * K + k0 + ac];
            ra1 = *(const float4*)&A[(size_t)(bm + ar) * K + k0 + ac + 4];
            rb0 = *(const float4*)&B[(size_t)(k0 + br) * N + bn + bc];
            rb1 = *(const float4*)&B[(size_t)(k0 + br) * N + bn + bc + 4];
        }
#pragma unroll
        for (int ks = 0; ks < 4; ks++) {
            int k8 = ks * 8;
            uint32_t ah[2][4], al[2][4], bh[2][2], bl[2][2];
#pragma unroll
            for (int ma = 0; ma < 2; ma++) {
                int m0 = wm * 32 + ma * 16 + gid;
                ah[ma][0] = Ah[m0][k8 + tig];     al[ma][0] = Al[m0][k8 + tig];
                ah[ma][1] = Ah[m0 + 8][k8 + tig]; al[ma][1] = Al[m0 + 8][k8 + tig];
                ah[ma][2] = Ah[m0][k8 + tig + 4]; al[ma][2] = Al[m0][k8 + tig + 4];
                ah[ma][3] = Ah[m0 + 8][k8 + tig + 4]; al[ma][3] = Al[m0 + 8][k8 + tig + 4];
            }
#pragma unroll
            for (int na = 0; na < 2; na++) {
                int n0 = wn * 16 + na * 8 + gid;
                bh[na][0] = Bh[k8 + tig][n0];     bl[na][0] = Bl[k8 + tig][n0];
                bh[na][1] = Bh[k8 + tig + 4][n0]; bl[na][1] = Bl[k8 + tig + 4][n0];
            }
#pragma unroll
            for (int ma = 0; ma < 2; ma++)
#pragma unroll
                for (int na = 0; na < 2; na++)
                    mma3(c[ma][na], ah[ma], al[ma], bh[na], bl[na]);
        }
    }

#pragma unroll
    for (int ma = 0; ma < 2; ma++)
#pragma unroll
        for (int na = 0; na < 2; na++) {
            int row = bm + wm * 32 + ma * 16 + gid;
            int col = bn + wn * 16 + na * 8 + 2 * tig;
            float2 bv = *(const float2*)&bias[col];
            float2 o0; o0.x = c[ma][na][0] + bv.x; o0.y = c[ma][na][1] + bv.y;
            float2 o1; o1.x = c[ma][na][2] + bv.x; o1.y = c[ma][na][3] + bv.y;
            *(float2*)&C[(size_t)row * N + col]       = o0;
            *(float2*)&C[(size_t)(row + 8) * N + col] = o1;
        }
}

// ---------- K2 tensor: qk[s][h][j] = Q_h[s,:] . Wk_h[j,:]  (K=32) -------
__global__ void __launch_bounds__(256)
k_qk_tf32(const float* __restrict__ Wkv, const float* __restrict__ bkv) {
    __shared__ uint32_t Ah[64][36], Al[64][36];   // q slice  [s][d]
    __shared__ uint32_t Nh[64][36], Nl[64][36];   // Wk slice [j][d]
    int t = threadIdx.x;
    int lane = t & 31, w = t >> 5;
    int gid = lane >> 2, tig = lane & 3;
    int wm = w & 1, wn = w >> 1;
    int bm = blockIdx.x * 64, bnj = blockIdx.y * 64, h = blockIdx.z;
    int r = t >> 2, cq = (t & 3) * 8;

    {
        float4 v0 = *(const float4*)&g_q[(size_t)(bm + r) * H_DIM + h * HD + cq];
        float4 v1 = *(const float4*)&g_q[(size_t)(bm + r) * H_DIM + h * HD + cq + 4];
        uint4 hh, ll;
        split4(v0, hh, ll); *(uint4*)&Ah[r][cq] = hh;     *(uint4*)&Al[r][cq] = ll;
        split4(v1, hh, ll); *(uint4*)&Ah[r][cq + 4] = hh; *(uint4*)&Al[r][cq + 4] = ll;
        float4 w0 = *(const float4*)&Wkv[(size_t)(bnj + r) * 512 + h * HD + cq];
        float4 w1 = *(const float4*)&Wkv[(size_t)(bnj + r) * 512 + h * HD + cq + 4];
        split4(w0, hh, ll); *(uint4*)&Nh[r][cq] = hh;     *(uint4*)&Nl[r][cq] = ll;
        split4(w1, hh, ll); *(uint4*)&Nh[r][cq + 4] = hh; *(uint4*)&Nl[r][cq + 4] = ll;
    }
    __syncthreads();

    float c[2][2][4] = {};
#pragma unroll
    for (int ks = 0; ks < 4; ks++) {
        int k8 = ks * 8;
        uint32_t ah[2][4], al[2][4], bh[2][2], bl[2][2];
#pragma unroll
        for (int ma = 0; ma < 2; ma++) {
            int m0 = wm * 32 + ma * 16 + gid;
            ah[ma][0] = Ah[m0][k8 + tig];         al[ma][0] = Al[m0][k8 + tig];
            ah[ma][1] = Ah[m0 + 8][k8 + tig];     al[ma][1] = Al[m0 + 8][k8 + tig];
            ah[ma][2] = Ah[m0][k8 + tig + 4];     al[ma][2] = Al[m0][k8 + tig + 4];
            ah[ma][3] = Ah[m0 + 8][k8 + tig + 4]; al[ma][3] = Al[m0 + 8][k8 + tig + 4];
        }
#pragma unroll
        for (int na = 0; na < 2; na++) {
            int n0 = wn * 16 + na * 8 + gid;
            bh[na][0] = Nh[n0][k8 + tig];     bl[na][0] = Nl[n0][k8 + tig];
            bh[na][1] = Nh[n0][k8 + tig + 4]; bl[na][1] = Nl[n0][k8 + tig + 4];
        }
#pragma unroll
        for (int ma = 0; ma < 2; ma++)
#pragma unroll
            for (int na = 0; na < 2; na++)
                mma3(c[ma][na], ah[ma], al[ma], bh[na], bl[na]);
    }

#pragma unroll
    for (int ma = 0; ma < 2; ma++)
#pragma unroll
        for (int na = 0; na < 2; na++) {
            int srow = bm + wm * 32 + ma * 16 + gid;
            int col  = bnj + wn * 16 + na * 8 + 2 * tig;
            float2 o0; o0.x = c[ma][na][0]; o0.y = c[ma][na][1];
            float2 o1; o1.x = c[ma][na][2]; o1.y = c[ma][na][3];
            *(float2*)&g_qk[(size_t)srow * (NH * D_DIM) + h * D_DIM + col]       = o0;
            *(float2*)&g_qk[(size_t)(srow + 8) * (NH * D_DIM) + h * D_DIM + col] = o1;
        }

    if (blockIdx.y == 0 && t < 64) {
        int s = bm + t;
        float acc = 0.f;
#pragma unroll
        for (int d = 0; d < HD; d++)
            acc += g_q[(size_t)s * H_DIM + h * HD + d] * bkv[h * HD + d];
        g_qb[s * NH + h] = acc;
    }
}

// ---------- K4 tensor: pooled_h = Ahat_h[64x256] @ Wv_h[256x32] ---------
__global__ void __launch_bounds__(256)
k_pool_tf32(const float* __restrict__ Wkv, const float* __restrict__ bkv) {
    __shared__ uint32_t Ah[64][36], Al[64][36];
    __shared__ uint32_t Bh[32][40], Bl[32][40];
    int t = threadIdx.x;
    int lane = t & 31, w = t >> 5;
    int gid = lane >> 2, tig = lane & 3;
    int wm = w & 3, wn = w >> 2;
    int bm = blockIdx.x * 64, h = blockIdx.y;
    int arr = t >> 2, acq = (t & 3) * 8;
    int bkk = t >> 3, bn4 = (t & 7) * 4;

    const __half* Abase = g_Ahat + (size_t)bm * (NH * D_DIM) + h * D_DIM;
    float c[2][4] = {};
    uint4 rha;
    float4 rb;

    rha = *(const uint4*)&Abase[(size_t)arr * (NH * D_DIM) + acq];
    rb  = *(const float4*)&Wkv[(size_t)bkk * 512 + 256 + h * HD + bn4];

    for (int ch = 0; ch < 8; ch++) {
        if (ch > 0) __syncthreads();
        {
            float4 ra0, ra1;
            half8_to_f4(rha, ra0, ra1);
            uint4 hh, ll;
            split4(ra0, hh, ll);
            *(uint4*)&Ah[arr][acq] = hh;     *(uint4*)&Al[arr][acq] = ll;
            split4(ra1, hh, ll);
            *(uint4*)&Ah[arr][acq + 4] = hh; *(uint4*)&Al[arr][acq + 4] = ll;
            split4(rb, hh, ll);
            *(uint4*)&Bh[bkk][bn4] = hh;     *(uint4*)&Bl[bkk][bn4] = ll;
        }
        __syncthreads();
        if (ch + 1 < 8) {
            int k0 = (ch + 1) * 32;
            rha = *(const uint4*)&Abase[(size_t)arr * (NH * D_DIM) + k0 + acq];
            rb  = *(const float4*)&Wkv[(size_t)(k0 + bkk) * 512 + 256 + h * HD + bn4];
        }
#pragma unroll
        for (int ks = 0; ks < 4; ks++) {
            int k8 = ks * 8;
            uint32_t ah[4], al[4], bh[2][2], bl[2][2];
            int m0 = wm * 16 + gid;
            ah[0] = Ah[m0][k8 + tig];         al[0] = Al[m0][k8 + tig];
            ah[1] = Ah[m0 + 8][k8 + tig];     al[1] = Al[m0 + 8][k8 + tig];
            ah[2] = Ah[m0][k8 + tig + 4];     al[2] = Al[m0][k8 + tig + 4];
            ah[3] = Ah[m0 + 8][k8 + tig + 4]; al[3] = Al[m0 + 8][k8 + tig + 4];
#pragma unroll
            for (int na = 0; na < 2; na++) {
                int n0 = wn * 16 + na * 8 + gid;
                bh[na][0] = Bh[k8 + tig][n0];     bl[na][0] = Bl[k8 + tig][n0];
                bh[na][1] = Bh[k8 + tig + 4][n0]; bl[na][1] = Bl[k8 + tig + 4][n0];
            }
#pragma unroll
            for (int na = 0; na < 2; na++)
                mma3(c[na], ah, al, bh[na], bl[na]);
        }
    }

#pragma unroll
    for (int na = 0; na < 2; na++) {
        int row = bm + wm * 16 + gid;
        int col = wn * 16 + na * 8 + 2 * tig;
        float2 bv = *(const float2*)&bkv[256 + h * HD + col];
        bool ne0 = g_off[row + 1] > g_off[row];
        bool ne1 = g_off[row + 9] > g_off[row + 8];
        float2 o0, o1;
        o0.x = c[na][0] + (ne0 ? bv.x : 0.f); o0.y = c[na][1] + (ne0 ? bv.y : 0.f);
        o1.x = c[na][2] + (ne1 ? bv.x : 0.f); o1.y = c[na][3] + (ne1 ? bv.y : 0.f);
        *(float2*)&g_pooled[(size_t)row * H_DIM + h * HD + col]       = o0;
        *(float2*)&g_pooled[(size_t)(row + 8) * H_DIM + h * HD + col] = o1;
    }
}

// ---------------- K3: streaming softmax-pool accumulation ---------------
// R15 structure (4096 blocks, 4/SM) + two isolated tweaks from R16:
//  * prologue qk/qb loaded via cp.async (no LDG->STS register round trip;
//    drains in the same wait as the first E tile)
//  * d accumulated lane-locally per tile, warp-reduced ONCE per sample
// Unconditional CPA_WAIT0+sync before the epilogue drains the prologue
// group for empty segments.
#define ATTN_SMEM_FLOATS (12896)
#define SE_STRIDE 260

__global__ void __launch_bounds__(256, 4)
k_attn(const float* __restrict__ emb, float scale) {
    extern __shared__ float dyn[];
    float* sQK   = dyn;
    float* sE    = dyn + 2080;
    float* sPart = dyn + 10400;
    float* sP    = dyn + 12496;
    float* sD    = dyn + 12880;
    float* sQBs  = dyn + 12888;

    int s = blockIdx.x;
    int t = threadIdx.x;
    int lane = t & 31, w = t >> 5;
    int gid = lane >> 2, tig = lane & 3;

    int start = g_off[s], end = g_off[s + 1];

    // prologue: qk + qb + first E tile, all via cp.async, one group
    for (int i = t; i < 512; i += 256) {
        int h = i >> 6, j = (i & 63) * 4;
        cpa16(&sQK[h * SE_STRIDE + j], g_qk + (size_t)s * 2048 + (size_t)i * 4);
    }
    if (t < 2) cpa16(&sQBs[t * 4], g_qb + s * NH + t * 4);
    if (start < end) {
        int T = min(32, end - start);
        for (int i = t; i < T * 64; i += 256) {
            int e = i >> 6, j4 = (i & 63) * 4;
            cpa16(&sE[e * SE_STRIDE + j4],
                  emb + (size_t)(start + e) * D_DIM + j4);
        }
    }
    CPA_COMMIT();

    float c[2][4] = {};
    float d_lane = 0.f;
    int j0 = w * 32;

    for (int t0 = start; t0 < end; t0 += 32) {
        int T = min(32, end - t0);

        CPA_WAIT0();
        __syncthreads();   // tile (and on first pass, qk/qb) resident

        if (T < 32) {      // zero tail rows so 0*garbage can't make NaN
            for (int i = t; i < (32 - T) * 64; i += 256) {
                int e = T + (i >> 6), j4 = (i & 63) * 4;
                *(float4*)&sE[e * SE_STRIDE + j4] = make_float4(0.f, 0.f, 0.f, 0.f);
            }
            __syncthreads();
        }

        // ---- score partials via tensor cores
        {
            float cs[2][4] = {};
#pragma unroll
            for (int ks = 0; ks < 4; ks++) {
                int jk = j0 + ks * 8;
                uint32_t bh[2], bl[2];
                tf32_split(sQK[gid * SE_STRIDE + jk + tig],     bh[0], bl[0]);
                tf32_split(sQK[gid * SE_STRIDE + jk + tig + 4], bh[1], bl[1]);
#pragma unroll
                for (int ma = 0; ma < 2; ma++) {
                    int e0 = ma * 16 + gid;
                    uint32_t ah[4], al[4];
                    tf32_split(sE[e0 * SE_STRIDE + jk + tig],           ah[0], al[0]);
                    tf32_split(sE[(e0 + 8) * SE_STRIDE + jk + tig],     ah[1], al[1]);
                    tf32_split(sE[e0 * SE_STRIDE + jk + tig + 4],       ah[2], al[2]);
                    tf32_split(sE[(e0 + 8) * SE_STRIDE + jk + tig + 4], ah[3], al[3]);
                    mma3(cs[ma], ah, al, bh, bl);
                }
            }
#pragma unroll
            for (int ma = 0; ma < 2; ma++) {
                int e0 = ma * 16 + gid;
                sPart[e0 * 65 + (2 * tig) * 8 + w]           = cs[ma][0];
                sPart[e0 * 65 + (2 * tig + 1) * 8 + w]       = cs[ma][1];
                sPart[(e0 + 8) * 65 + (2 * tig) * 8 + w]     = cs[ma][2];
                sPart[(e0 + 8) * 65 + (2 * tig + 1) * 8 + w] = cs[ma][3];
            }
        }
        __syncthreads();

        // ---- reduce partials + exp; d accumulated lane-locally
        float p = 0.f;
        if (lane < T) {
            float sum = 0.f;
#pragma unroll
            for (int i = 0; i < 8; i++) sum += sPart[lane * 65 + w * 8 + i];
            p = __expf(scale * (sum + sQBs[w]));
        }
        sP[lane * 12 + w] = p;
        d_lane += p;
        __syncthreads();

        // ---- A update via tensor cores
#pragma unroll
        for (int ks = 0; ks < 4; ks++) {
            int e0 = 8 * ks + tig;
            uint32_t bh[2], bl[2];
            tf32_split(sP[e0 * 12 + gid],       bh[0], bl[0]);
            tf32_split(sP[(e0 + 4) * 12 + gid], bh[1], bl[1]);
#pragma unroll
            for (int ma = 0; ma < 2; ma++) {
                int jbv = j0 + ma * 16 + gid;
                uint32_t ah[4], al[4];
                tf32_split(sE[e0 * SE_STRIDE + jbv],           ah[0], al[0]);
                tf32_split(sE[e0 * SE_STRIDE + jbv + 8],       ah[1], al[1]);
                tf32_split(sE[(e0 + 4) * SE_STRIDE + jbv],     ah[2], al[2]);
                tf32_split(sE[(e0 + 4) * SE_STRIDE + jbv + 8], ah[3], al[3]);
                mma3(c[ma], ah, al, bh, bl);
            }
        }
        __syncthreads();   // all sE reads done; safe to refill

        if (t0 + 32 < end) {
            int Tn = min(32, end - (t0 + 32));
            for (int i = t; i < Tn * 64; i += 256) {
                int e = i >> 6, j4 = (i & 63) * 4;
                cpa16(&sE[e * SE_STRIDE + j4],
                      emb + (size_t)(t0 + 32 + e) * D_DIM + j4);
            }
        }
        CPA_COMMIT();
    }

    // drain any pending prologue/final group (covers empty segments too)
    CPA_WAIT0();
    __syncthreads();

    // ---- once-per-sample d reduce + fp16 Ahat write
    {
        float dsum = d_lane;
#pragma unroll
        for (int o = 16; o; o >>= 1) dsum += __shfl_xor_sync(0xffffffffu, dsum, o);
        if (lane == 0) sD[w] = dsum;
    }
    __syncthreads();
    {
        float dh0 = sD[2 * tig],     rdh0 = (dh0 > 0.f) ? (1.0f / dh0) : 0.f;
        float dh1 = sD[2 * tig + 1], rdh1 = (dh1 > 0.f) ? (1.0f / dh1) : 0.f;
        __half* outp = g_Ahat + (size_t)s * (NH * D_DIM);
#pragma unroll
        for (int ma = 0; ma < 2; ma++) {
            int j = j0 + ma * 16 + gid;
            outp[(2 * tig) * D_DIM + j]         = __float2half_rn(c[ma][0] * rdh0);
            outp[(2 * tig + 1) * D_DIM + j]     = __float2half_rn(c[ma][1] * rdh1);
            outp[(2 * tig) * D_DIM + j + 8]     = __float2half_rn(c[ma][2] * rdh0);
            outp[(2 * tig + 1) * D_DIM + j + 8] = __float2half_rn(c[ma][3] * rdh1);
        }
    }
}

// ---------------- launch ----------------
extern "C" void kernel_launch(void* const* d_in, const int* in_sizes, int n_in,
                              void* d_out, int out_size) {
    const float* queries = (const float*)d_in[0];
    const float* emb     = (const float*)d_in[1];
    const int*   map     = (const int*)  d_in[2];
    // num_samples may or may not be materialized as a device input
    int base = (n_in >= 10 && in_sizes[3] < 16) ? 4 : 3;
    const float* Wq  = (const float*)d_in[base + 0];
    const float* bq  = (const float*)d_in[base + 1];
    const float* Wkv = (const float*)d_in[base + 2];
    const float* bkv = (const float*)d_in[base + 3];
    const float* Wo  = (const float*)d_in[base + 4];
    const float* bo  = (const float*)d_in[base + 5];
    float* out = (float*)d_out;

    int S = in_sizes[0] / D_DIM;     // 4096
    int N = in_sizes[1] / D_DIM;     // 262144
    float scale = 0.17677669529663687f;   // 1/sqrt(32)

    float* dq      = nullptr; cudaGetSymbolAddress((void**)&dq,      g_q);
    float* dpooled = nullptr; cudaGetSymbolAddress((void**)&dpooled, g_pooled);

    cudaFuncSetAttribute(k_attn, cudaFuncAttributeMaxDynamicSharedMemorySize,
                         ATTN_SMEM_FLOATS * 4);

    // K0: segment offsets
    k_offsets<<<(S + 1 + 255) / 256, 256>>>(map, N, S);
    // K1: q projection (tensor core, 3xTF32)
    {
        dim3 grid(S / 64, H_DIM / 64);
        k_gemm_tf32<<<grid, 256>>>(queries, Wq, bq, dq, S, D_DIM, H_DIM);
    }
    // K2: qk/qb precompute (tensor core)
    {
        dim3 grid(S / 64, D_DIM / 64, NH);
        k_qk_tf32<<<grid, 256>>>(Wkv, bkv);
    }
    // K3: streaming attention accumulation
    k_attn<<<S, 256, ATTN_SMEM_FLOATS * 4>>>(emb, scale);
    // K4: pooled projection through Wv (tensor core, fp16 Ahat read)
    {
        dim3 grid(S / 64, NH);
        k_pool_tf32<<<grid, 256>>>(Wkv, bkv);
    }
    // K5: output projection (tensor core, 3xTF32)
    {
        dim3 grid(S / 64, H_DIM / 64);
        k_gemm_tf32<<<grid, 256>>>(dpooled, Wo, bo, out, S, H_DIM, H_DIM);
    }
}